// round 4
// baseline (speedup 1.0000x reference)
#include <cuda_runtime.h>
#include <math.h>

#define VOCAB 10000

// ---------------- scratch (static device globals; no allocation) ----------------
static __device__ float    g_Gx[4096 * 1024];   // input-proj gates [row=b*64+t][1024]
static __device__ float    g_H[64 * 256];       // current hidden state [b][h]
static __device__ float    g_hs[4096 * 256];    // all hidden states [row][h]
static __device__ unsigned g_bar[64];           // per-step grid barrier counters
static __device__ float    g_pmax[79 * 4096];   // softmax partial max   [tile][row]
static __device__ float    g_psum[79 * 4096];   // softmax partial sumexp[tile][row]
static __device__ float    g_lt[4096];          // target logit per row

__device__ __forceinline__ float sigm(float x) { return 1.0f / (1.0f + expf(-x)); }

// ---------------- init: zero h0 and barrier counters (every launch) ----------------
__global__ void k_init()
{
    int t = blockIdx.x * blockDim.x + threadIdx.x;
    if (t < 64 * 256) g_H[t] = 0.0f;
    if (t < 64) g_bar[t] = 0u;
}

// ---------------- kA: embedding gather + X @ Wx + b  -> g_Gx ----------------
// rows = 4096 (r = b*64 + t), cols = 1024 gates, K = 256
__global__ void __launch_bounds__(256) kA(const int* __restrict__ idx,
                                          const float* __restrict__ E,
                                          const float* __restrict__ W,   // W_lstm [512][1024]
                                          const float* __restrict__ bl)
{
    __shared__ float As[16][68];   // [k][row]
    __shared__ float Bs[16][68];   // [k][col]
    const int tid = threadIdx.x;
    const int tx = tid & 15, ty = tid >> 4;
    const int ro = blockIdx.y * 64, co = blockIdx.x * 64;

    const int arow = tid >> 2;           // 0..63
    const int ak   = (tid & 3) << 2;     // 0,4,8,12
    const int erow = idx[ro + arow];     // embedding row
    const int bk   = tid >> 4;           // 0..15
    const int bc   = (tid & 15) << 2;    // 0..60

    float acc[4][4] = {};

    for (int k0 = 0; k0 < 256; k0 += 16) {
        float4 av = *(const float4*)(E + erow * 256 + k0 + ak);
        As[ak + 0][arow] = av.x; As[ak + 1][arow] = av.y;
        As[ak + 2][arow] = av.z; As[ak + 3][arow] = av.w;
        *(float4*)&Bs[bk][bc] = *(const float4*)(W + (k0 + bk) * 1024 + co + bc);
        __syncthreads();
#pragma unroll
        for (int k = 0; k < 16; k++) {
            float4 a4 = *(const float4*)&As[k][ty << 2];
            float4 b4 = *(const float4*)&Bs[k][tx << 2];
            float a[4] = {a4.x, a4.y, a4.z, a4.w};
            float b[4] = {b4.x, b4.y, b4.z, b4.w};
#pragma unroll
            for (int i = 0; i < 4; i++)
#pragma unroll
                for (int j = 0; j < 4; j++)
                    acc[i][j] = fmaf(a[i], b[j], acc[i][j]);
        }
        __syncthreads();
    }

    float bv[4];
#pragma unroll
    for (int j = 0; j < 4; j++) bv[j] = bl[co + (tx << 2) + j];
#pragma unroll
    for (int i = 0; i < 4; i++) {
        int r = ro + (ty << 2) + i;
        float* dst = &g_Gx[r * 1024 + co + (tx << 2)];
#pragma unroll
        for (int j = 0; j < 4; j++) dst[j] = acc[i][j] + bv[j];
    }
}

// ---------------- kB: persistent LSTM recurrence ----------------
// 128 CTAs = 8 batch-groups x 16 hid-groups. Each CTA: 8 batches x 16 hids.
// Weights register-stationary: thread (cg,kq) holds Wh[k=32*kq..+31][2 cols].
__global__ void __launch_bounds__(256) kB(const float* __restrict__ W)   // W_lstm
{
    __shared__ float s_h[8 * 256];       // staged h for this CTA's 8 batches
    __shared__ float s_p[8 * 64 * 8];    // partials [b][lc][kq]

    const int tid = threadIdx.x;
    const int bg = blockIdx.x >> 4;      // 0..7
    const int hg = blockIdx.x & 15;      // 0..15
    const int B0 = bg << 3;

    const int cg = tid & 31;             // col pair
    const int kq = tid >> 5;             // k-split 0..7
    const int lc0 = cg << 1;             // local col (even)
    const int gc0 = ((lc0 >> 4) << 8) + (hg << 4) + (lc0 & 15);  // global gate col

    float w0[32], w1[32];
#pragma unroll
    for (int kk = 0; kk < 32; kk++) {
        const float* wr = W + (256 + (kq << 5) + kk) * 1024 + gc0;
        w0[kk] = wr[0];
        w1[kk] = wr[1];
    }

    const int rb = tid >> 4, rh = tid & 15;   // reduce-phase identity (tid<128)
    const int ghid = (hg << 4) + rh;
    float c_state = 0.0f;

    for (int t = 0; t < 64; t++) {
        // stage h[8 batches][256] into smem (zero at t=0 via k_init)
#pragma unroll
        for (int v = 0; v < 2; v++) {
            int li = tid + (v << 8);          // float4 slot 0..511
            int b = li >> 6, k4 = li & 63;
            ((float4*)s_h)[(b << 6) + k4] = ((const float4*)g_H)[((B0 + b) << 6) + k4];
        }
        __syncthreads();

        float acc0[8], acc1[8];
#pragma unroll
        for (int b = 0; b < 8; b++) {
            const float4* hp = (const float4*)(s_h + (b << 8) + (kq << 5));
            float a0 = 0.0f, a1 = 0.0f;
#pragma unroll
            for (int q = 0; q < 8; q++) {
                float4 h4 = hp[q];
                a0 = fmaf(h4.x, w0[4 * q + 0], a0); a1 = fmaf(h4.x, w1[4 * q + 0], a1);
                a0 = fmaf(h4.y, w0[4 * q + 1], a0); a1 = fmaf(h4.y, w1[4 * q + 1], a1);
                a0 = fmaf(h4.z, w0[4 * q + 2], a0); a1 = fmaf(h4.z, w1[4 * q + 2], a1);
                a0 = fmaf(h4.w, w0[4 * q + 3], a0); a1 = fmaf(h4.w, w1[4 * q + 3], a1);
            }
            acc0[b] = a0; acc1[b] = a1;
        }
#pragma unroll
        for (int b = 0; b < 8; b++) {
            s_p[((b << 6) + lc0) * 8 + kq]       = acc0[b];
            s_p[((b << 6) + lc0 + 1) * 8 + kq]   = acc1[b];
        }
        __syncthreads();

        if (tid < 128) {
            float sg[4];
#pragma unroll
            for (int g = 0; g < 4; g++) {
                const float* pp = s_p + (((rb << 6) + (g << 4) + rh) << 3);
                float4 p0 = *(const float4*)pp;
                float4 p1 = *(const float4*)(pp + 4);
                sg[g] = ((p0.x + p0.y) + (p0.z + p0.w)) + ((p1.x + p1.y) + (p1.z + p1.w));
            }
            const float* gx = g_Gx + (((B0 + rb) << 6) + t) * 1024 + ghid;
            float vi = sg[0] + gx[0];
            float vj = sg[1] + gx[256];
            float vf = sg[2] + gx[512];
            float vo = sg[3] + gx[768];
            c_state = sigm(vf + 1.0f) * c_state + sigm(vi) * tanhf(vj);
            float h = sigm(vo) * tanhf(c_state);
            g_H[((B0 + rb) << 8) + ghid] = h;
            g_hs[(((B0 + rb) << 6) + t) * 256 + ghid] = h;
        }

        if (t < 63) {   // grid barrier between steps
            __threadfence();
            __syncthreads();
            if (tid == 0) {
                atomicAdd(&g_bar[t], 1u);
                volatile unsigned* p = &g_bar[t];
                while (*p < 128u) { }
                __threadfence();
            }
            __syncthreads();
        }
    }
}

// ---------------- kC: hs @ W_dense + b, fused online-softmax partials ----------------
// grid (79 col-tiles, 32 row-tiles), 128x128 tile, K=256, 8x8 micro
__global__ void __launch_bounds__(256) kC(const float* __restrict__ Wd,
                                          const float* __restrict__ bd,
                                          const int* __restrict__ tgt)
{
    __shared__ float sm[4224];           // union: As[16][132]+Bs[16][132] | red[128][16]x2
    float* As = sm;
    float* Bs = sm + 2112;
    const int tid = threadIdx.x;
    const int tx = tid & 15, ty = tid >> 4;
    const int ro = blockIdx.y << 7;
    const int co = blockIdx.x << 7;

    const int lrow = tid >> 1;           // A-load row
    const int lkb  = (tid & 1) << 3;     // A-load k base
    const int bk   = tid >> 4;           // B-load k
    const int bcb  = (tid & 15) << 3;    // B-load col base
    const bool tail = (co + 128 > VOCAB);

    float acc[8][8] = {};

    for (int k0 = 0; k0 < 256; k0 += 16) {
        {   // A: g_hs[row][k] -> As[k][row] (transposed)
            const float* src = g_hs + (ro + lrow) * 256 + k0 + lkb;
            float4 v0 = *(const float4*)src;
            float4 v1 = *(const float4*)(src + 4);
            float* d = As + lrow;
            d[(lkb + 0) * 132] = v0.x; d[(lkb + 1) * 132] = v0.y;
            d[(lkb + 2) * 132] = v0.z; d[(lkb + 3) * 132] = v0.w;
            d[(lkb + 4) * 132] = v1.x; d[(lkb + 5) * 132] = v1.y;
            d[(lkb + 6) * 132] = v1.z; d[(lkb + 7) * 132] = v1.w;
        }
        {   // B: W_dense[k][col] -> Bs[k][col]
            const float* src = Wd + (k0 + bk) * VOCAB + co + bcb;
            float* d = Bs + bk * 132 + bcb;
            if (!tail) {
                *(float4*)d       = *(const float4*)src;
                *(float4*)(d + 4) = *(const float4*)(src + 4);
            } else {
#pragma unroll
                for (int e = 0; e < 8; e++)
                    d[e] = (co + bcb + e < VOCAB) ? src[e] : 0.0f;
            }
        }
        __syncthreads();
#pragma unroll
        for (int k = 0; k < 16; k++) {
            float4 a0 = *(const float4*)(As + k * 132 + (ty << 3));
            float4 a1 = *(const float4*)(As + k * 132 + (ty << 3) + 4);
            float4 b0 = *(const float4*)(Bs + k * 132 + (tx << 3));
            float4 b1 = *(const float4*)(Bs + k * 132 + (tx << 3) + 4);
            float a[8] = {a0.x, a0.y, a0.z, a0.w, a1.x, a1.y, a1.z, a1.w};
            float b[8] = {b0.x, b0.y, b0.z, b0.w, b1.x, b1.y, b1.z, b1.w};
#pragma unroll
            for (int i = 0; i < 8; i++)
#pragma unroll
                for (int j = 0; j < 8; j++)
                    acc[i][j] = fmaf(a[i], b[j], acc[i][j]);
        }
        __syncthreads();
    }

    // epilogue: bias, target-logit capture, per-thread row max/sumexp
    float bias[8];
    bool valid[8];
#pragma unroll
    for (int j = 0; j < 8; j++) {
        int gc = co + (tx << 3) + j;
        valid[j] = (gc < VOCAB);
        bias[j] = valid[j] ? bd[gc] : 0.0f;
    }
    float m[8], s[8];
#pragma unroll
    for (int i = 0; i < 8; i++) {
        int gr = ro + (ty << 3) + i;
        int tg = tgt[gr];
        float mi = -1e30f;
#pragma unroll
        for (int j = 0; j < 8; j++) {
            float l = valid[j] ? (acc[i][j] + bias[j]) : -1e30f;
            acc[i][j] = l;
            if (valid[j] && (co + (tx << 3) + j) == tg) g_lt[gr] = l;
            mi = fmaxf(mi, l);
        }
        float si = 0.0f;
#pragma unroll
        for (int j = 0; j < 8; j++) si += __expf(acc[i][j] - mi);
        m[i] = mi; s[i] = si;
    }

    __syncthreads();   // reuse smem for reduction
    float* redm = sm;          // [128][16]
    float* reds = sm + 2048;   // [128][16]
#pragma unroll
    for (int i = 0; i < 8; i++) {
        redm[((ty << 3) + i) * 16 + tx] = m[i];
        reds[((ty << 3) + i) * 16 + tx] = s[i];
    }
    __syncthreads();
    if (tid < 128) {
        float M = -1e30f;
#pragma unroll
        for (int x = 0; x < 16; x++) M = fmaxf(M, redm[tid * 16 + x]);
        float S = 0.0f;
#pragma unroll
        for (int x = 0; x < 16; x++) S += reds[tid * 16 + x] * __expf(redm[tid * 16 + x] - M);
        g_pmax[blockIdx.x * 4096 + ro + tid] = M;
        g_psum[blockIdx.x * 4096 + ro + tid] = S;
    }
}

// ---------------- kD: combine partials -> perplexity ----------------
__global__ void kD(float* __restrict__ out)
{
    int r = blockIdx.x * 128 + threadIdx.x;   // = b*64 + t, matches out[b][t]
    float M = g_pmax[r];
    float S = g_psum[r];
    for (int i = 1; i < 79; i++) {
        float mi = g_pmax[i * 4096 + r];
        float si = g_psum[i * 4096 + r];
        float nm = fmaxf(M, mi);
        S = S * __expf(M - nm) + si * __expf(mi - nm);
        M = nm;
    }
    out[r] = S * __expf(M - g_lt[r]);   // ppl = sumexp * exp(max - target_logit)
}

// ---------------- launch ----------------
extern "C" void kernel_launch(void* const* d_in, const int* in_sizes, int n_in,
                              void* d_out, int out_size)
{
    const int*   input_data = (const int*)d_in[0];
    const int*   targets    = (const int*)d_in[1];
    const float* E          = (const float*)d_in[2];
    const float* W_lstm     = (const float*)d_in[3];
    const float* b_lstm     = (const float*)d_in[4];
    const float* W_dense    = (const float*)d_in[5];
    const float* b_dense    = (const float*)d_in[6];
    float* out = (float*)d_out;
    (void)in_sizes; (void)n_in; (void)out_size; (void)b_lstm;

    k_init<<<64, 256>>>();
    kA<<<dim3(16, 64), 256>>>(input_data, E, W_lstm, b_lstm);
    kB<<<128, 256>>>(W_lstm);
    kC<<<dim3(79, 32), 256>>>(W_dense, b_dense, targets);
    kD<<<32, 128>>>(out);
}